// round 3
// baseline (speedup 1.0000x reference)
#include <cuda_runtime.h>
#include <cstdio>

// ---------------- problem constants ----------------
#define BB   2048          // batch / num nodes
#define TT   64            // seq len
#define EE   300           // embed dim = hidden
#define HH   300
#define G4   1200          // 4*H
#define D2   600           // 2*H
#define CC   1024          // num classes
#define NEDGE 65536
#define BT   (BB*TT)       // 131072
#define KCOS (TT*D2)       // 38400

// ---------------- scratch (device globals; no cudaMalloc allowed) ----------------
__device__ float g_emb[(size_t)BT * EE];            // [BT, 300]
__device__ float g_gi [(size_t)2 * BT * G4];        // [2][BT, 1200] precomputed input gates
__device__ float g_c  [(size_t)BT * D2];            // [B, T, 600] LSTM outputs (then normalized)
__device__ float g_h  [(size_t)2 * BB * HH];        // [2][B, 300] hidden state
__device__ float g_cs [(size_t)2 * BB * HH];        // [2][B, 300] cell state
__device__ float g_gg [(size_t)2 * BB * G4];        // [2][B, 1200] per-step recurrent GEMM out
__device__ float g_lnn[(size_t)CC * D2];            // normalized label emb
__device__ float g_hn [(size_t)BB * CC];            // node features h (ls -> updated)
__device__ float g_m  [(size_t)BB * CC];            // message GEMM out
__device__ float g_agg[(size_t)BB * CC];            // scatter-add target
__device__ float g_gru[(size_t)2 * BB * 3072];      // [gi ; gh]

// ---------------- helpers ----------------
__device__ __forceinline__ float sigf(float x) { return 1.0f / (1.0f + __expf(-x)); }
__device__ __forceinline__ float tanhfast(float x) {
    // tanh(x) = 2*sigmoid(2x)-1 ; saturates correctly for large |x|
    return 2.0f / (1.0f + __expf(-2.0f * x)) - 1.0f;
}

__global__ void zerok(float* __restrict__ p, int n) {
    int i = blockIdx.x * blockDim.x + threadIdx.x;
    if (i < n) p[i] = 0.0f;
}

// ---------------- embedding gather: g_emb[row] = table[x[row]] ----------------
__global__ void emb_gather(const int* __restrict__ x, const float* __restrict__ tbl) {
    int i = blockIdx.x * blockDim.x + threadIdx.x;
    if (i >= BT * (EE / 4)) return;
    int row = i / (EE / 4);
    int e4  = (i - row * (EE / 4)) * 4;
    int idx = x[row];
    *(float4*)&g_emb[(size_t)row * EE + e4] =
        *(const float4*)&tbl[(size_t)idx * EE + e4];
}

// ---------------- generic tiled SGEMM ----------------
// C[M,N] = A[M,K] * op(B)
//   BLAY=0 (NT): B is [N,K] row-major (x @ W^T style)
//   BLAY=1 (NN): B is [K,N] row-major
//   MODK>0: B's K index is (k % MODK), B row stride = MODK (requires K%8==0)
//   BIASF:  add bias[col]
// gridDim.z = batch; pointers (A0,B0,C0)/(A1,B1,C1) selected by blockIdx.z.
template<int BLAY, int MODK, int BIASF>
__global__ void __launch_bounds__(256)
sgemm(const float* __restrict__ A0, const float* __restrict__ B0, float* __restrict__ C0,
      const float* __restrict__ A1, const float* __restrict__ B1, float* __restrict__ C1,
      const float* __restrict__ bias, int M, int N, int K)
{
    const float* A = blockIdx.z ? A1 : A0;
    const float* Bm = blockIdx.z ? B1 : B0;
    float*       C = blockIdx.z ? C1 : C0;

    __shared__ float As[8][128];
    __shared__ float Bs[8][128];

    const int tid = threadIdx.x;
    const int bm = blockIdx.y * 128;
    const int bn = blockIdx.x * 128;
    const int tx = tid & 15;     // 0..15 -> n
    const int ty = tid >> 4;     // 0..15 -> m

    const int ar = tid >> 1;          // 0..127
    const int ac = (tid & 1) * 4;     // 0 or 4
    const int bkk = tid >> 5;         // 0..7  (NN)
    const int bnn = (tid & 31) * 4;   // 0..124 (NN)

    float acc[8][8];
    #pragma unroll
    for (int i = 0; i < 8; i++)
        #pragma unroll
        for (int j = 0; j < 8; j++) acc[i][j] = 0.0f;

    for (int k0 = 0; k0 < K; k0 += 8) {
        // ---- A tile ----
        {
            int row = bm + ar;
            int k = k0 + ac;
            float4 v = make_float4(0.f, 0.f, 0.f, 0.f);
            if (row < M) {
                const float* ap = A + (size_t)row * K;
                if (k + 3 < K)       v = *(const float4*)(ap + k);
                else {
                    if (k     < K) v.x = ap[k];
                    if (k + 1 < K) v.y = ap[k + 1];
                    if (k + 2 < K) v.z = ap[k + 2];
                }
            }
            As[ac + 0][ar] = v.x; As[ac + 1][ar] = v.y;
            As[ac + 2][ar] = v.z; As[ac + 3][ar] = v.w;
        }
        // ---- B tile ----
        if (BLAY == 0) {
            int row = bn + ar;
            int k = k0 + ac;
            float4 v = make_float4(0.f, 0.f, 0.f, 0.f);
            if (row < N) {
                if (MODK > 0) {
                    int d = k % MODK;   // start aligned to 4, MODK%4==0 -> no wrap inside float4
                    v = *(const float4*)(Bm + (size_t)row * MODK + d);
                } else {
                    const float* bp = Bm + (size_t)row * K;
                    if (k + 3 < K)   v = *(const float4*)(bp + k);
                    else {
                        if (k     < K) v.x = bp[k];
                        if (k + 1 < K) v.y = bp[k + 1];
                        if (k + 2 < K) v.z = bp[k + 2];
                    }
                }
            }
            Bs[ac + 0][ar] = v.x; Bs[ac + 1][ar] = v.y;
            Bs[ac + 2][ar] = v.z; Bs[ac + 3][ar] = v.w;
        } else {
            int k = k0 + bkk;
            int col = bn + bnn;
            float4 v = make_float4(0.f, 0.f, 0.f, 0.f);
            if (k < K) {
                const float* bp = Bm + (size_t)k * N;
                if (col + 3 < N) v = *(const float4*)(bp + col);
                else {
                    if (col     < N) v.x = bp[col];
                    if (col + 1 < N) v.y = bp[col + 1];
                    if (col + 2 < N) v.z = bp[col + 2];
                }
            }
            *(float4*)&Bs[bkk][bnn] = v;
        }
        __syncthreads();

        // ---- compute 8x8 per thread ----
        #pragma unroll
        for (int kk = 0; kk < 8; kk++) {
            float a[8], b[8];
            *(float4*)&a[0] = *(const float4*)&As[kk][ty * 8];
            *(float4*)&a[4] = *(const float4*)&As[kk][ty * 8 + 4];
            *(float4*)&b[0] = *(const float4*)&Bs[kk][tx * 8];
            *(float4*)&b[4] = *(const float4*)&Bs[kk][tx * 8 + 4];
            #pragma unroll
            for (int i = 0; i < 8; i++)
                #pragma unroll
                for (int j = 0; j < 8; j++)
                    acc[i][j] += a[i] * b[j];
        }
        __syncthreads();
    }

    // ---- store ----
    #pragma unroll
    for (int i = 0; i < 8; i++) {
        int row = bm + ty * 8 + i;
        if (row < M) {
            #pragma unroll
            for (int j = 0; j < 8; j++) {
                int col = bn + tx * 8 + j;
                if (col < N) {
                    float v = acc[i][j];
                    if (BIASF) v += bias[col];
                    C[(size_t)row * N + col] = v;
                }
            }
        }
    }
}

// ---------------- LSTM gates (both directions in one launch) ----------------
__global__ void lstm_gates(const float* __restrict__ bih_f, const float* __restrict__ bhh_f,
                           const float* __restrict__ bih_b, const float* __restrict__ bhh_b,
                           int s)
{
    int i = blockIdx.x * blockDim.x + threadIdx.x;
    if (i >= 2 * BB * HH) return;
    int dir = i / (BB * HH);
    int r   = i - dir * (BB * HH);
    int b   = r / HH;
    int j   = r - b * HH;
    int t   = dir ? (TT - 1 - s) : s;

    const float* bi = dir ? bih_b : bih_f;
    const float* bh = dir ? bhh_b : bhh_f;

    size_t gb  = (size_t)dir * BB * G4 + (size_t)b * G4;
    size_t gib = (size_t)dir * BT * G4 + ((size_t)b * TT + t) * G4;

    float xi = g_gg[gb +        j] + g_gi[gib +        j] + bi[j]        + bh[j];
    float xf = g_gg[gb +  HH  + j] + g_gi[gib +  HH  + j] + bi[HH + j]   + bh[HH + j];
    float xg = g_gg[gb + 2*HH + j] + g_gi[gib + 2*HH + j] + bi[2*HH + j] + bh[2*HH + j];
    float xo = g_gg[gb + 3*HH + j] + g_gi[gib + 3*HH + j] + bi[3*HH + j] + bh[3*HH + j];

    float ig = sigf(xi), fg = sigf(xf), cg = tanhfast(xg), og = sigf(xo);

    size_t hidx = (size_t)dir * BB * HH + r;
    float cn = fg * g_cs[hidx] + ig * cg;
    float hn = og * tanhfast(cn);
    g_cs[hidx] = cn;
    g_h[hidx]  = hn;
    g_c[((size_t)b * TT + t) * D2 + dir * HH + j] = hn;
}

// ---------------- row L2-normalize (warp per row) ----------------
__global__ void rownorm(const float* __restrict__ in, float* __restrict__ out, int R, int W) {
    int warp = threadIdx.x >> 5;
    int lane = threadIdx.x & 31;
    int row = blockIdx.x * 8 + warp;
    if (row >= R) return;
    const float* p = in + (size_t)row * W;
    float ss = 0.f;
    for (int c = lane; c < W; c += 32) { float v = p[c]; ss += v * v; }
    #pragma unroll
    for (int o = 16; o; o >>= 1) ss += __shfl_xor_sync(0xffffffffu, ss, o);
    float scale = 1.0f / fmaxf(sqrtf(ss), 1e-8f);
    float* q = out + (size_t)row * W;
    for (int c = lane; c < W; c += 32) q[c] = p[c] * scale;
}

// ---------------- edge scatter-add: agg[dst] += m[src] ----------------
__global__ void scatter_add(const int* __restrict__ ei) {
    int i = blockIdx.x * blockDim.x + threadIdx.x;
    if (i >= NEDGE * (CC / 4)) return;
    int e  = i >> 8;           // CC/4 = 256
    int c4 = (i & 255) << 2;
    int src = ei[e];
    int dst = ei[NEDGE + e];
    float4 v = *(const float4*)&g_m[(size_t)src * CC + c4];
    float* a = &g_agg[(size_t)dst * CC + c4];
    atomicAdd(a + 0, v.x); atomicAdd(a + 1, v.y);
    atomicAdd(a + 2, v.z); atomicAdd(a + 3, v.w);
}

// ---------------- GRU cell update (in-place on g_hn) ----------------
__global__ void gru_gates(const float* __restrict__ bih, const float* __restrict__ bhh) {
    int i = blockIdx.x * blockDim.x + threadIdx.x;
    if (i >= BB * CC) return;
    int b = i >> 10;
    int j = i & 1023;
    size_t gb = (size_t)b * 3072;
    size_t gh = (size_t)BB * 3072 + gb;

    float ir = g_gru[gb +        j] + bih[j];
    float iz = g_gru[gb + 1024 + j] + bih[1024 + j];
    float in_ = g_gru[gb + 2048 + j] + bih[2048 + j];
    float hr = g_gru[gh +        j] + bhh[j];
    float hz = g_gru[gh + 1024 + j] + bhh[1024 + j];
    float hn = g_gru[gh + 2048 + j] + bhh[2048 + j];

    float r = sigf(ir + hr);
    float z = sigf(iz + hz);
    float n = tanhfast(in_ + r * hn);
    float h = g_hn[i];
    g_hn[i] = (1.0f - z) * n + z * h;
}

// ---------------- orchestration ----------------
extern "C" void kernel_launch(void* const* d_in, const int* in_sizes, int n_in,
                              void* d_out, int out_size)
{
    const int*   x        = (const int*)d_in[0];
    const int*   ei       = (const int*)d_in[1];
    const float* emb_tab  = (const float*)d_in[2];
    const float* Wih_f    = (const float*)d_in[3];
    const float* Whh_f    = (const float*)d_in[4];
    const float* bih_f    = (const float*)d_in[5];
    const float* bhh_f    = (const float*)d_in[6];
    const float* Wih_b    = (const float*)d_in[7];
    const float* Whh_b    = (const float*)d_in[8];
    const float* bih_b    = (const float*)d_in[9];
    const float* bhh_b    = (const float*)d_in[10];
    const float* label    = (const float*)d_in[11];
    const float* ggc_w    = (const float*)d_in[12];
    const float* gru_Wih  = (const float*)d_in[13];
    const float* gru_Whh  = (const float*)d_in[14];
    const float* gru_bih  = (const float*)d_in[15];
    const float* gru_bhh  = (const float*)d_in[16];
    const float* proj_W   = (const float*)d_in[17];
    const float* proj_b   = (const float*)d_in[18];
    float* out = (float*)d_out;

    float *p_emb, *p_gi, *p_c, *p_h, *p_cs, *p_gg, *p_lnn, *p_hn, *p_m, *p_agg, *p_gru;
    cudaGetSymbolAddress((void**)&p_emb, g_emb);
    cudaGetSymbolAddress((void**)&p_gi,  g_gi);
    cudaGetSymbolAddress((void**)&p_c,   g_c);
    cudaGetSymbolAddress((void**)&p_h,   g_h);
    cudaGetSymbolAddress((void**)&p_cs,  g_cs);
    cudaGetSymbolAddress((void**)&p_gg,  g_gg);
    cudaGetSymbolAddress((void**)&p_lnn, g_lnn);
    cudaGetSymbolAddress((void**)&p_hn,  g_hn);
    cudaGetSymbolAddress((void**)&p_m,   g_m);
    cudaGetSymbolAddress((void**)&p_agg, g_agg);
    cudaGetSymbolAddress((void**)&p_gru, g_gru);

    const int TPB = 256;

    // 0) zero LSTM states
    zerok<<<(2 * BB * HH + TPB - 1) / TPB, TPB>>>(p_h, 2 * BB * HH);
    zerok<<<(2 * BB * HH + TPB - 1) / TPB, TPB>>>(p_cs, 2 * BB * HH);

    // 1) embedding gather
    emb_gather<<<(BT * (EE / 4) + TPB - 1) / TPB, TPB>>>(x, emb_tab);

    // 2) input-to-hidden GEMMs, both directions: [BT,300] x [300->1200]
    {
        dim3 grid((G4 + 127) / 128, (BT + 127) / 128, 2);
        sgemm<0, 0, 0><<<grid, 256>>>(p_emb, Wih_f, p_gi,
                                      p_emb, Wih_b, p_gi + (size_t)BT * G4,
                                      nullptr, BT, G4, EE);
    }

    // 3) recurrence: 64 steps, both directions batched (z=2)
    for (int s = 0; s < TT; s++) {
        dim3 grid((G4 + 127) / 128, (BB + 127) / 128, 2);
        sgemm<0, 0, 0><<<grid, 256>>>(p_h,                     Whh_f, p_gg,
                                      p_h + (size_t)BB * HH,   Whh_b, p_gg + (size_t)BB * G4,
                                      nullptr, BB, G4, HH);
        lstm_gates<<<(2 * BB * HH + TPB - 1) / TPB, TPB>>>(bih_f, bhh_f, bih_b, bhh_b, s);
    }

    // 4) normalize c rows (in place) and label rows
    rownorm<<<(BT + 7) / 8, 256>>>(p_c, p_c, BT, D2);
    rownorm<<<(CC + 7) / 8, 256>>>(label, p_lnn, CC, D2);

    // 5) cosine similarity folded GEMM: [B, 38400] x periodic [1024, 600]
    {
        dim3 grid((CC + 127) / 128, (BB + 127) / 128, 1);
        sgemm<0, D2, 0><<<grid, 256>>>(p_c, p_lnn, p_hn,
                                       p_c, p_lnn, p_hn,
                                       nullptr, BB, CC, KCOS);
    }

    // 6) GatedGraphConv, 2 layers
    for (int layer = 0; layer < 2; layer++) {
        // m = h @ W[layer]   (NN)
        {
            dim3 grid((CC + 127) / 128, (BB + 127) / 128, 1);
            sgemm<1, 0, 0><<<grid, 256>>>(p_hn, ggc_w + (size_t)layer * CC * CC, p_m,
                                          p_hn, ggc_w + (size_t)layer * CC * CC, p_m,
                                          nullptr, BB, CC, CC);
        }
        // scatter-add
        zerok<<<(BB * CC + TPB - 1) / TPB, TPB>>>(p_agg, BB * CC);
        scatter_add<<<(NEDGE * (CC / 4) + TPB - 1) / TPB, TPB>>>(ei);
        // GRU gate GEMMs (z=0: agg@Wih^T, z=1: h@Whh^T)
        {
            dim3 grid((3072 + 127) / 128, (BB + 127) / 128, 2);
            sgemm<0, 0, 0><<<grid, 256>>>(p_agg, gru_Wih, p_gru,
                                          p_hn,  gru_Whh, p_gru + (size_t)BB * 3072,
                                          nullptr, BB, 3072, CC);
        }
        gru_gates<<<(BB * CC + TPB - 1) / TPB, TPB>>>(gru_bih, gru_bhh);
    }

    // 7) projection with bias -> d_out
    {
        dim3 grid((CC + 127) / 128, (BB + 127) / 128, 1);
        sgemm<0, 0, 1><<<grid, 256>>>(p_hn, proj_W, out,
                                      p_hn, proj_W, out,
                                      proj_b, BB, CC, CC);
    }
}

// round 5
// speedup vs baseline: 1.5815x; 1.5815x over previous
#include <cuda_runtime.h>

// ---------------- problem constants ----------------
#define BB   2048          // batch / num nodes
#define TT   64            // seq len
#define EE   300           // embed dim = hidden
#define HH   300
#define G4   1200          // 4*H
#define D2   600           // 2*H
#define CC   1024          // num classes
#define NEDGE 65536
#define BT   (BB*TT)       // 131072
#define KCOS (TT*D2)       // 38400

// ---------------- scratch (device globals; no cudaMalloc allowed) ----------------
__device__ float g_emb[(size_t)BT * EE];
__device__ float g_gi [(size_t)2 * BT * G4];
__device__ float g_c  [(size_t)BT * D2];
__device__ float g_h  [(size_t)2 * BB * HH];
__device__ float g_cs [(size_t)2 * BB * HH];
__device__ float g_gg [(size_t)2 * BB * G4];
__device__ float g_lnn[(size_t)CC * D2];
__device__ float g_hn [(size_t)BB * CC];
__device__ float g_m  [(size_t)BB * CC];
__device__ float g_agg[(size_t)BB * CC];
__device__ float g_gru[(size_t)2 * BB * 3072];

// ---------------- helpers ----------------
__device__ __forceinline__ float sigf(float x) { return 1.0f / (1.0f + __expf(-x)); }
__device__ __forceinline__ float tanhfast(float x) {
    return 2.0f / (1.0f + __expf(-2.0f * x)) - 1.0f;
}

__global__ void zerok(float* __restrict__ p, int n) {
    int i = blockIdx.x * blockDim.x + threadIdx.x;
    if (i < n) p[i] = 0.0f;
}

// ---------------- embedding gather ----------------
__global__ void emb_gather(const int* __restrict__ x, const float* __restrict__ tbl) {
    int i = blockIdx.x * blockDim.x + threadIdx.x;
    if (i >= BT * (EE / 4)) return;
    int row = i / (EE / 4);
    int e4  = (i - row * (EE / 4)) * 4;
    int idx = x[row];
    *(float4*)&g_emb[(size_t)row * EE + e4] =
        *(const float4*)&tbl[(size_t)idx * EE + e4];
}

// ---------------- tensor-core GEMM (3xTF32, fp32-accurate) ----------------
// C[M,N] = A[M,K] * op(B)
//   BLAY=0 (NT): B is [N,K] row-major    BLAY=1 (NN): B is [K,N] row-major
//   MODK>0:  B's K index is (k % MODK), B row stride = MODK (NT only)
//   BIASF:   add bias[col]
//   SPLITK>1: grid.z splits K; epilogue atomicAdd (C must be pre-zeroed).
//   SPLITK==1: grid.z selects instance (A0,B0,C0)/(A1,B1,C1).
#define PADLD 132

__device__ __forceinline__ void tf32split(float v, float& hi, float& lo) {
    hi = __uint_as_float(__float_as_uint(v) & 0xffffe000u);
    lo = v - hi;
}

__device__ __forceinline__ void mma_tf32(float* d, const float* a, const float* b) {
    const unsigned* A = reinterpret_cast<const unsigned*>(a);
    const unsigned* B = reinterpret_cast<const unsigned*>(b);
    asm volatile(
        "mma.sync.aligned.m16n8k8.row.col.f32.tf32.tf32.f32 "
        "{%0,%1,%2,%3},{%4,%5,%6,%7},{%8,%9},{%0,%1,%2,%3};\n"
        : "+f"(d[0]), "+f"(d[1]), "+f"(d[2]), "+f"(d[3])
        : "r"(A[0]), "r"(A[1]), "r"(A[2]), "r"(A[3]),
          "r"(B[0]), "r"(B[1]));
}

template<int BLAY, int MODK, int BIASF, int SPLITK>
__global__ void __launch_bounds__(256, 1)
gemm_tc(const float* __restrict__ A0, const float* __restrict__ B0, float* __restrict__ C0,
        const float* __restrict__ A1, const float* __restrict__ B1, float* __restrict__ C1,
        const float* __restrict__ bias, int M, int N, int K)
{
    __shared__ float As[2][16 * PADLD];
    __shared__ float Bs[2][16 * PADLD];

    const float* A; const float* Bm; float* C;
    int kbeg, kend;
    if (SPLITK > 1) {
        A = A0; Bm = B0; C = C0;
        int ks = K / SPLITK;            // caller guarantees K % (16*SPLITK) == 0
        kbeg = blockIdx.z * ks;
        kend = kbeg + ks;
    } else {
        A  = blockIdx.z ? A1 : A0;
        Bm = blockIdx.z ? B1 : B0;
        C  = blockIdx.z ? C1 : C0;
        kbeg = 0; kend = K;
    }

    const int t  = threadIdx.x;
    const int bm = blockIdx.y * 128;
    const int bn = blockIdx.x * 128;

    // loader mappings (NT: k-major transpose store; NN: row-of-k store)
    const int lr  = t & 127;
    const int lk  = (t >> 7) * 8;
    const int kk2 = t >> 4;            // NN: k row 0..15
    const int nb  = (t & 15) * 8;      // NN: n base

    const int wid  = t >> 5;
    const int wm   = wid >> 1;         // 0..3 (M)
    const int wn   = wid & 1;          // 0..1 (N)
    const int lane = t & 31;
    const int r = lane >> 2;           // 0..7
    const int c = lane & 3;            // 0..3

    float acc[2][8][4];
    #pragma unroll
    for (int i = 0; i < 2; i++)
        #pragma unroll
        for (int j = 0; j < 8; j++)
            #pragma unroll
            for (int q = 0; q < 4; q++) acc[i][j][q] = 0.0f;

    auto gload = [&](int k0, float4* ra, float4* rb) {
        // A tile [128 rows x 16 k]
        {
            int row = bm + lr;
            const float* ap = A + (size_t)row * K;
            #pragma unroll
            for (int q = 0; q < 2; q++) {
                int k = k0 + lk + q * 4;
                float4 v = make_float4(0.f, 0.f, 0.f, 0.f);
                if (row < M) {
                    if (k + 3 < kend) v = *(const float4*)(ap + k);
                    else {
                        if (k     < kend) v.x = ap[k];
                        if (k + 1 < kend) v.y = ap[k + 1];
                        if (k + 2 < kend) v.z = ap[k + 2];
                    }
                }
                ra[q] = v;
            }
        }
        if (BLAY == 0) {
            int row = bn + lr;
            #pragma unroll
            for (int q = 0; q < 2; q++) {
                int k = k0 + lk + q * 4;
                float4 v = make_float4(0.f, 0.f, 0.f, 0.f);
                if (row < N) {
                    if (MODK > 0) {
                        // k aligned to 4, MODK % 4 == 0 -> float4 never wraps
                        v = *(const float4*)(Bm + (size_t)row * MODK + (k % MODK));
                    } else {
                        const float* bp = Bm + (size_t)row * K;
                        if (k + 3 < kend) v = *(const float4*)(bp + k);
                        else {
                            if (k     < kend) v.x = bp[k];
                            if (k + 1 < kend) v.y = bp[k + 1];
                            if (k + 2 < kend) v.z = bp[k + 2];
                        }
                    }
                }
                rb[q] = v;
            }
        } else {
            #pragma unroll
            for (int q = 0; q < 2; q++) {
                int k = k0 + kk2;
                int col = bn + nb + q * 4;
                float4 v = make_float4(0.f, 0.f, 0.f, 0.f);
                if (k < kend) {
                    const float* bp = Bm + (size_t)k * N;
                    if (col + 3 < N) v = *(const float4*)(bp + col);
                    else {
                        if (col     < N) v.x = bp[col];
                        if (col + 1 < N) v.y = bp[col + 1];
                        if (col + 2 < N) v.z = bp[col + 2];
                    }
                }
                rb[q] = v;
            }
        }
    };

    auto sts = [&](int buf, const float4* ra, const float4* rb) {
        #pragma unroll
        for (int q = 0; q < 2; q++) {
            As[buf][(lk + q * 4 + 0) * PADLD + lr] = ra[q].x;
            As[buf][(lk + q * 4 + 1) * PADLD + lr] = ra[q].y;
            As[buf][(lk + q * 4 + 2) * PADLD + lr] = ra[q].z;
            As[buf][(lk + q * 4 + 3) * PADLD + lr] = ra[q].w;
        }
        if (BLAY == 0) {
            #pragma unroll
            for (int q = 0; q < 2; q++) {
                Bs[buf][(lk + q * 4 + 0) * PADLD + lr] = rb[q].x;
                Bs[buf][(lk + q * 4 + 1) * PADLD + lr] = rb[q].y;
                Bs[buf][(lk + q * 4 + 2) * PADLD + lr] = rb[q].z;
                Bs[buf][(lk + q * 4 + 3) * PADLD + lr] = rb[q].w;
            }
        } else {
            #pragma unroll
            for (int q = 0; q < 2; q++)
                *(float4*)&Bs[buf][kk2 * PADLD + nb + q * 4] = rb[q];
        }
    };

    float4 ra[2], rb[2];
    gload(kbeg, ra, rb);
    sts(0, ra, rb);
    __syncthreads();

    int cur = 0;
    for (int k0 = kbeg; k0 < kend; k0 += 16) {
        bool more = (k0 + 16) < kend;
        if (more) gload(k0 + 16, ra, rb);

        #pragma unroll
        for (int sub = 0; sub < 2; sub++) {
            const int ko = sub * 8;
            // B fragments for 8 n-tiles
            float bh[8][2], bl[8][2];
            #pragma unroll
            for (int nt = 0; nt < 8; nt++) {
                int colb = wn * 64 + nt * 8 + r;
                float v0 = Bs[cur][(ko + c)     * PADLD + colb];
                float v1 = Bs[cur][(ko + c + 4) * PADLD + colb];
                tf32split(v0, bh[nt][0], bl[nt][0]);
                tf32split(v1, bh[nt][1], bl[nt][1]);
            }
            #pragma unroll
            for (int mt = 0; mt < 2; mt++) {
                int m0 = wm * 32 + mt * 16;
                float a0 = As[cur][(ko + c)     * PADLD + m0 + r];
                float a1 = As[cur][(ko + c)     * PADLD + m0 + r + 8];
                float a2 = As[cur][(ko + c + 4) * PADLD + m0 + r];
                float a3 = As[cur][(ko + c + 4) * PADLD + m0 + r + 8];
                float ah[4], al[4];
                tf32split(a0, ah[0], al[0]);
                tf32split(a1, ah[1], al[1]);
                tf32split(a2, ah[2], al[2]);
                tf32split(a3, ah[3], al[3]);
                #pragma unroll
                for (int nt = 0; nt < 8; nt++) {
                    mma_tf32(acc[mt][nt], ah, bh[nt]);  // hi*hi
                    mma_tf32(acc[mt][nt], al, bh[nt]);  // lo*hi
                    mma_tf32(acc[mt][nt], ah, bl[nt]);  // hi*lo
                }
            }
        }

        if (more) sts(cur ^ 1, ra, rb);
        __syncthreads();
        cur ^= 1;
    }

    // ---- epilogue ----
    #pragma unroll
    for (int mt = 0; mt < 2; mt++) {
        #pragma unroll
        for (int nt = 0; nt < 8; nt++) {
            int row0 = bm + wm * 32 + mt * 16 + r;
            int col0 = bn + wn * 64 + nt * 8 + c * 2;
            #pragma unroll
            for (int h = 0; h < 2; h++) {
                int row = row0 + h * 8;
                if (row < M) {
                    #pragma unroll
                    for (int w = 0; w < 2; w++) {
                        int col = col0 + w;
                        if (col < N) {
                            float v = acc[mt][nt][h * 2 + w];
                            if (BIASF) v += bias[col];
                            if (SPLITK > 1) atomicAdd(&C[(size_t)row * N + col], v);
                            else            C[(size_t)row * N + col] = v;
                        }
                    }
                }
            }
        }
    }
}

// ---------------- LSTM gates (both directions in one launch) ----------------
__global__ void lstm_gates(const float* __restrict__ bih_f, const float* __restrict__ bhh_f,
                           const float* __restrict__ bih_b, const float* __restrict__ bhh_b,
                           int s)
{
    int i = blockIdx.x * blockDim.x + threadIdx.x;
    if (i >= 2 * BB * HH) return;
    int dir = i / (BB * HH);
    int rr  = i - dir * (BB * HH);
    int b   = rr / HH;
    int j   = rr - b * HH;
    int tt  = dir ? (TT - 1 - s) : s;

    const float* bi = dir ? bih_b : bih_f;
    const float* bh = dir ? bhh_b : bhh_f;

    size_t gb  = (size_t)dir * BB * G4 + (size_t)b * G4;
    size_t gib = (size_t)dir * BT * G4 + ((size_t)b * TT + tt) * G4;

    float xi = g_gg[gb +        j] + g_gi[gib +        j] + bi[j]          + bh[j];
    float xf = g_gg[gb +  HH  + j] + g_gi[gib +  HH  + j] + bi[HH + j]     + bh[HH + j];
    float xg = g_gg[gb + 2*HH + j] + g_gi[gib + 2*HH + j] + bi[2*HH + j]   + bh[2*HH + j];
    float xo = g_gg[gb + 3*HH + j] + g_gi[gib + 3*HH + j] + bi[3*HH + j]   + bh[3*HH + j];

    float ig = sigf(xi), fg = sigf(xf), cg = tanhfast(xg), og = sigf(xo);

    size_t hidx = (size_t)dir * BB * HH + rr;
    float cn = fg * g_cs[hidx] + ig * cg;
    float hn = og * tanhfast(cn);
    g_cs[hidx] = cn;
    g_h[hidx]  = hn;
    g_c[((size_t)b * TT + tt) * D2 + dir * HH + j] = hn;
}

// ---------------- row L2-normalize (warp per row) ----------------
__global__ void rownorm(const float* __restrict__ in, float* __restrict__ out, int R, int W) {
    int warp = threadIdx.x >> 5;
    int lane = threadIdx.x & 31;
    int row = blockIdx.x * 8 + warp;
    if (row >= R) return;
    const float* p = in + (size_t)row * W;
    float ss = 0.f;
    for (int cc = lane; cc < W; cc += 32) { float v = p[cc]; ss += v * v; }
    #pragma unroll
    for (int o = 16; o; o >>= 1) ss += __shfl_xor_sync(0xffffffffu, ss, o);
    float scale = 1.0f / fmaxf(sqrtf(ss), 1e-8f);
    float* q = out + (size_t)row * W;
    for (int cc = lane; cc < W; cc += 32) q[cc] = p[cc] * scale;
}

// ---------------- edge scatter-add: agg[dst] += m[src] ----------------
__global__ void scatter_add(const int* __restrict__ ei) {
    int i = blockIdx.x * blockDim.x + threadIdx.x;
    if (i >= NEDGE * (CC / 4)) return;
    int e  = i >> 8;
    int c4 = (i & 255) << 2;
    int src = ei[e];
    int dst = ei[NEDGE + e];
    float4 v = *(const float4*)&g_m[(size_t)src * CC + c4];
    float* a = &g_agg[(size_t)dst * CC + c4];
    atomicAdd(a + 0, v.x); atomicAdd(a + 1, v.y);
    atomicAdd(a + 2, v.z); atomicAdd(a + 3, v.w);
}

// ---------------- GRU cell update (in-place on g_hn) ----------------
__global__ void gru_gates(const float* __restrict__ bih, const float* __restrict__ bhh) {
    int i = blockIdx.x * blockDim.x + threadIdx.x;
    if (i >= BB * CC) return;
    int b = i >> 10;
    int j = i & 1023;
    size_t gb = (size_t)b * 3072;
    size_t gh = (size_t)BB * 3072 + gb;

    float ir  = g_gru[gb +        j] + bih[j];
    float iz  = g_gru[gb + 1024 + j] + bih[1024 + j];
    float in_ = g_gru[gb + 2048 + j] + bih[2048 + j];
    float hr  = g_gru[gh +        j] + bhh[j];
    float hz  = g_gru[gh + 1024 + j] + bhh[1024 + j];
    float hn  = g_gru[gh + 2048 + j] + bhh[2048 + j];

    float rg = sigf(ir + hr);
    float zg = sigf(iz + hz);
    float ng = tanhfast(in_ + rg * hn);
    float h = g_hn[i];
    g_hn[i] = (1.0f - zg) * ng + zg * h;
}

// ---------------- orchestration ----------------
extern "C" void kernel_launch(void* const* d_in, const int* in_sizes, int n_in,
                              void* d_out, int out_size)
{
    const int*   x        = (const int*)d_in[0];
    const int*   ei       = (const int*)d_in[1];
    const float* emb_tab  = (const float*)d_in[2];
    const float* Wih_f    = (const float*)d_in[3];
    const float* Whh_f    = (const float*)d_in[4];
    const float* bih_f    = (const float*)d_in[5];
    const float* bhh_f    = (const float*)d_in[6];
    const float* Wih_b    = (const float*)d_in[7];
    const float* Whh_b    = (const float*)d_in[8];
    const float* bih_b    = (const float*)d_in[9];
    const float* bhh_b    = (const float*)d_in[10];
    const float* label    = (const float*)d_in[11];
    const float* ggc_w    = (const float*)d_in[12];
    const float* gru_Wih  = (const float*)d_in[13];
    const float* gru_Whh  = (const float*)d_in[14];
    const float* gru_bih  = (const float*)d_in[15];
    const float* gru_bhh  = (const float*)d_in[16];
    const float* proj_W   = (const float*)d_in[17];
    const float* proj_b   = (const float*)d_in[18];
    float* out = (float*)d_out;

    float *p_emb, *p_gi, *p_c, *p_h, *p_cs, *p_gg, *p_lnn, *p_hn, *p_m, *p_agg, *p_gru;
    cudaGetSymbolAddress((void**)&p_emb, g_emb);
    cudaGetSymbolAddress((void**)&p_gi,  g_gi);
    cudaGetSymbolAddress((void**)&p_c,   g_c);
    cudaGetSymbolAddress((void**)&p_h,   g_h);
    cudaGetSymbolAddress((void**)&p_cs,  g_cs);
    cudaGetSymbolAddress((void**)&p_gg,  g_gg);
    cudaGetSymbolAddress((void**)&p_lnn, g_lnn);
    cudaGetSymbolAddress((void**)&p_hn,  g_hn);
    cudaGetSymbolAddress((void**)&p_m,   g_m);
    cudaGetSymbolAddress((void**)&p_agg, g_agg);
    cudaGetSymbolAddress((void**)&p_gru, g_gru);

    const int TPB = 256;

    // 0) zero LSTM states
    zerok<<<(2 * BB * HH + TPB - 1) / TPB, TPB>>>(p_h, 2 * BB * HH);
    zerok<<<(2 * BB * HH + TPB - 1) / TPB, TPB>>>(p_cs, 2 * BB * HH);

    // 1) embedding gather
    emb_gather<<<(BT * (EE / 4) + TPB - 1) / TPB, TPB>>>(x, emb_tab);

    // 2) input-to-hidden GEMMs, both directions: [BT,300] x [300->1200]  (NT)
    {
        dim3 grid((G4 + 127) / 128, (BT + 127) / 128, 2);
        gemm_tc<0, 0, 0, 1><<<grid, 256>>>(p_emb, Wih_f, p_gi,
                                           p_emb, Wih_b, p_gi + (size_t)BT * G4,
                                           nullptr, BT, G4, EE);
    }

    // 3) recurrence: 64 steps, both directions batched (z=2)
    for (int s = 0; s < TT; s++) {
        dim3 grid((G4 + 127) / 128, (BB + 127) / 128, 2);
        gemm_tc<0, 0, 0, 1><<<grid, 256>>>(p_h,                   Whh_f, p_gg,
                                           p_h + (size_t)BB * HH, Whh_b, p_gg + (size_t)BB * G4,
                                           nullptr, BB, G4, HH);
        lstm_gates<<<(2 * BB * HH + TPB - 1) / TPB, TPB>>>(bih_f, bhh_f, bih_b, bhh_b, s);
    }

    // 4) normalize c rows (in place) and label rows
    rownorm<<<(BT + 7) / 8, 256>>>(p_c, p_c, BT, D2);
    rownorm<<<(CC + 7) / 8, 256>>>(label, p_lnn, CC, D2);

    // 5) cosine similarity folded GEMM: [B, 38400] x periodic [1024, 600], split-K x4
    zerok<<<(BB * CC + TPB - 1) / TPB, TPB>>>(p_hn, BB * CC);
    {
        dim3 grid((CC + 127) / 128, (BB + 127) / 128, 4);
        gemm_tc<0, D2, 0, 4><<<grid, 256>>>(p_c, p_lnn, p_hn,
                                            p_c, p_lnn, p_hn,
                                            nullptr, BB, CC, KCOS);
    }

    // 6) GatedGraphConv, 2 layers
    for (int layer = 0; layer < 2; layer++) {
        // m = h @ W[layer]   (NN)
        {
            dim3 grid((CC + 127) / 128, (BB + 127) / 128, 1);
            gemm_tc<1, 0, 0, 1><<<grid, 256>>>(p_hn, ggc_w + (size_t)layer * CC * CC, p_m,
                                               p_hn, ggc_w + (size_t)layer * CC * CC, p_m,
                                               nullptr, BB, CC, CC);
        }
        // scatter-add
        zerok<<<(BB * CC + TPB - 1) / TPB, TPB>>>(p_agg, BB * CC);
        scatter_add<<<(NEDGE * (CC / 4) + TPB - 1) / TPB, TPB>>>(ei);
        // GRU gate GEMMs (z=0: agg@Wih^T, z=1: h@Whh^T)
        {
            dim3 grid((3072 + 127) / 128, (BB + 127) / 128, 2);
            gemm_tc<0, 0, 0, 1><<<grid, 256>>>(p_agg, gru_Wih, p_gru,
                                               p_hn,  gru_Whh, p_gru + (size_t)BB * 3072,
                                               nullptr, BB, 3072, CC);
        }
        gru_gates<<<(BB * CC + TPB - 1) / TPB, TPB>>>(gru_bih, gru_bhh);
    }

    // 7) projection with bias -> d_out
    {
        dim3 grid((CC + 127) / 128, (BB + 127) / 128, 1);
        gemm_tc<0, 0, 1, 1><<<grid, 256>>>(p_hn, proj_W, out,
                                           p_hn, proj_W, out,
                                           proj_b, BB, CC, CC);
    }
}

// round 7
// speedup vs baseline: 1.8977x; 1.1999x over previous
#include <cuda_runtime.h>
#include <cuda_bf16.h>

// ---------------- problem constants ----------------
#define BB   2048          // batch / num nodes
#define TT   64            // seq len
#define EE   300           // embed dim = hidden
#define HH   300
#define G4   1200          // 4*H
#define D2   600           // 2*H
#define CC   1024          // num classes
#define NEDGE 65536
#define BT   (BB*TT)       // 131072
#define KCOS (TT*D2)       // 38400

// ---------------- scratch (device globals; no cudaMalloc allowed) ----------------
__device__ float g_gi [(size_t)2 * BT * G4];
__device__ float g_c  [(size_t)BT * D2];
__device__ float g_h  [(size_t)2 * BB * HH];
__device__ float g_cs [(size_t)2 * BB * HH];
__device__ float g_gg [(size_t)2 * BB * G4];
__device__ float g_lnn[(size_t)CC * D2];
__device__ float g_hn [(size_t)BB * CC];
__device__ float g_m  [(size_t)BB * CC];
__device__ float g_agg[(size_t)BB * CC];
__device__ float g_gru[(size_t)2 * BB * 3072];

// ---------------- helpers ----------------
__device__ __forceinline__ float sigf(float x) { return 1.0f / (1.0f + __expf(-x)); }
__device__ __forceinline__ float tanhfast(float x) {
    return 2.0f / (1.0f + __expf(-2.0f * x)) - 1.0f;
}

__global__ void zerok(float* __restrict__ p, int n) {
    int i = blockIdx.x * blockDim.x + threadIdx.x;
    if (i < n) p[i] = 0.0f;
}

// ---------------- bf16 split helpers ----------------
// pack (x,y) into bf16x2 hi word; lo word holds residuals (also bf16x2)
__device__ __forceinline__ unsigned pack_hilo(float x, float y, unsigned& lo) {
    __nv_bfloat16 hx = __float2bfloat16_rn(x);
    __nv_bfloat16 hy = __float2bfloat16_rn(y);
    __nv_bfloat16 lx = __float2bfloat16_rn(x - __bfloat162float(hx));
    __nv_bfloat16 ly = __float2bfloat16_rn(y - __bfloat162float(hy));
    __nv_bfloat162 h2 = __halves2bfloat162(hx, hy);
    __nv_bfloat162 l2 = __halves2bfloat162(lx, ly);
    lo = *reinterpret_cast<unsigned*>(&l2);
    return *reinterpret_cast<unsigned*>(&h2);
}

__device__ __forceinline__ void mma_bf16(float* d, const unsigned* a, const unsigned* b) {
    asm volatile(
        "mma.sync.aligned.m16n8k16.row.col.f32.bf16.bf16.f32 "
        "{%0,%1,%2,%3},{%4,%5,%6,%7},{%8,%9},{%0,%1,%2,%3};\n"
        : "+f"(d[0]), "+f"(d[1]), "+f"(d[2]), "+f"(d[3])
        : "r"(a[0]), "r"(a[1]), "r"(a[2]), "r"(a[3]),
          "r"(b[0]), "r"(b[1]));
}

// ---------------- tensor-core GEMM (3xBF16, ~fp32-accurate) ----------------
// C[M,N] = A[M,K] * op(B)
//   BLAY=0 (NT): B is [N,K] row-major    BLAY=1 (NN): B is [K,N] row-major
//   MODK>0:  B's K index is (k % MODK), B row stride = MODK (NT only)
//   BIASF:   add bias[col]
//   SPLITK>1: grid.z splits K; epilogue atomicAdd (C pre-zeroed)
//   GIDX:    A row r reads A + gidx[r]*K (fused embedding gather)
// smem: kpair-major bf16x2, stride PADW words -> conflict-free frags & stores
#define PADW 136

template<int BLAY, int MODK, int BIASF, int SPLITK, int GIDX>
__global__ void __launch_bounds__(256, 1)
gemm_bf(const float* __restrict__ A0, const float* __restrict__ B0, float* __restrict__ C0,
        const float* __restrict__ A1, const float* __restrict__ B1, float* __restrict__ C1,
        const float* __restrict__ bias, const int* __restrict__ gidx,
        int M, int N, int K)
{
    __shared__ __align__(16) unsigned AsH[2][8 * PADW];
    __shared__ __align__(16) unsigned AsL[2][8 * PADW];
    __shared__ __align__(16) unsigned BsH[2][8 * PADW];
    __shared__ __align__(16) unsigned BsL[2][8 * PADW];

    const float* A; const float* Bm; float* C;
    int kbeg, kend;
    if (SPLITK > 1) {
        A = A0; Bm = B0; C = C0;
        int ks = K / SPLITK;            // caller guarantees K % (16*SPLITK) == 0
        kbeg = blockIdx.z * ks;
        kend = kbeg + ks;
    } else {
        A  = blockIdx.z ? A1 : A0;
        Bm = blockIdx.z ? B1 : B0;
        C  = blockIdx.z ? C1 : C0;
        kbeg = 0; kend = K;
    }

    const int t  = threadIdx.x;
    const int bm = blockIdx.y * 128;
    const int bn = blockIdx.x * 128;

    // loader mappings
    const int lr = t & 127;            // row (A) / col (B-NT)
    const int lk = (t >> 7) * 8;       // k offset 0 or 8
    const int lp = t >> 5;             // NN: kpair 0..7
    const int lc = (t & 31) * 4;       // NN: col base

    const int wid  = t >> 5;
    const int wm   = wid >> 1;         // 0..3 (M)
    const int wn   = wid & 1;          // 0..1 (N)
    const int lane = t & 31;
    const int g   = lane >> 2;         // 0..7
    const int tig = lane & 3;          // 0..3

    float acc[2][8][4];
    #pragma unroll
    for (int i = 0; i < 2; i++)
        #pragma unroll
        for (int j = 0; j < 8; j++)
            #pragma unroll
            for (int q = 0; q < 4; q++) acc[i][j][q] = 0.0f;

    float4 ra[2], rb[2];

    auto gload = [&](int k0) {
        // ---- A tile [128 rows x 16 k] ----
        {
            int row = bm + lr;
            const float* ap = nullptr;
            if (row < M) {
                long arow = GIDX ? (long)gidx[row] : (long)row;
                ap = A + (size_t)arow * K;
            }
            #pragma unroll
            for (int q = 0; q < 2; q++) {
                int k = k0 + lk + q * 4;
                float4 v = make_float4(0.f, 0.f, 0.f, 0.f);
                if (ap) {
                    if (k + 3 < kend) v = *(const float4*)(ap + k);
                    else {
                        if (k     < kend) v.x = ap[k];
                        if (k + 1 < kend) v.y = ap[k + 1];
                        if (k + 2 < kend) v.z = ap[k + 2];
                    }
                }
                ra[q] = v;
            }
        }
        // ---- B tile ----
        if (BLAY == 0) {
            int row = bn + lr;
            #pragma unroll
            for (int q = 0; q < 2; q++) {
                int k = k0 + lk + q * 4;
                float4 v = make_float4(0.f, 0.f, 0.f, 0.f);
                if (row < N) {
                    if (MODK > 0) {
                        v = *(const float4*)(Bm + (size_t)row * MODK + (k % MODK));
                    } else {
                        const float* bp = Bm + (size_t)row * K;
                        if (k + 3 < kend) v = *(const float4*)(bp + k);
                        else {
                            if (k     < kend) v.x = bp[k];
                            if (k + 1 < kend) v.y = bp[k + 1];
                            if (k + 2 < kend) v.z = bp[k + 2];
                        }
                    }
                }
                rb[q] = v;
            }
        } else {
            // NN: thread owns kpair lp (k rows k0+2lp, k0+2lp+1), cols lc..lc+3
            #pragma unroll
            for (int q = 0; q < 2; q++) {
                int k = k0 + 2 * lp + q;
                float4 v = make_float4(0.f, 0.f, 0.f, 0.f);
                if (k < kend) {
                    const float* bp = Bm + (size_t)k * N;
                    int col = bn + lc;
                    if (col + 3 < N) v = *(const float4*)(bp + col);
                    else {
                        if (col     < N) v.x = bp[col];
                        if (col + 1 < N) v.y = bp[col + 1];
                        if (col + 2 < N) v.z = bp[col + 2];
                    }
                }
                rb[q] = v;
            }
        }
    };

    auto sts = [&](int buf) {
        // A: pairs along k
        #pragma unroll
        for (int q = 0; q < 2; q++) {
            int p = (lk >> 1) + 2 * q;
            unsigned lo0, lo1;
            unsigned h0 = pack_hilo(ra[q].x, ra[q].y, lo0);
            unsigned h1 = pack_hilo(ra[q].z, ra[q].w, lo1);
            AsH[buf][p * PADW + lr]       = h0;
            AsL[buf][p * PADW + lr]       = lo0;
            AsH[buf][(p + 1) * PADW + lr] = h1;
            AsL[buf][(p + 1) * PADW + lr] = lo1;
        }
        if (BLAY == 0) {
            #pragma unroll
            for (int q = 0; q < 2; q++) {
                int p = (lk >> 1) + 2 * q;
                unsigned lo0, lo1;
                unsigned h0 = pack_hilo(rb[q].x, rb[q].y, lo0);
                unsigned h1 = pack_hilo(rb[q].z, rb[q].w, lo1);
                BsH[buf][p * PADW + lr]       = h0;
                BsL[buf][p * PADW + lr]       = lo0;
                BsH[buf][(p + 1) * PADW + lr] = h1;
                BsL[buf][(p + 1) * PADW + lr] = lo1;
            }
        } else {
            // pairs are (k even, k odd) at each col
            uint4 h4, l4;
            h4.x = pack_hilo(rb[0].x, rb[1].x, l4.x);
            h4.y = pack_hilo(rb[0].y, rb[1].y, l4.y);
            h4.z = pack_hilo(rb[0].z, rb[1].z, l4.z);
            h4.w = pack_hilo(rb[0].w, rb[1].w, l4.w);
            *(uint4*)&BsH[buf][lp * PADW + lc] = h4;
            *(uint4*)&BsL[buf][lp * PADW + lc] = l4;
        }
    };

    gload(kbeg);
    sts(0);
    __syncthreads();

    int cur = 0;
    for (int k0 = kbeg; k0 < kend; k0 += 16) {
        bool more = (k0 + 16) < kend;
        if (more) gload(k0 + 16);

        // ---- B fragments (8 n-tiles, hi+lo) ----
        unsigned bh[8][2], bl[8][2];
        #pragma unroll
        for (int nt = 0; nt < 8; nt++) {
            int col = wn * 64 + nt * 8 + g;
            bh[nt][0] = BsH[cur][tig * PADW + col];
            bh[nt][1] = BsH[cur][(tig + 4) * PADW + col];
            bl[nt][0] = BsL[cur][tig * PADW + col];
            bl[nt][1] = BsL[cur][(tig + 4) * PADW + col];
        }
        #pragma unroll
        for (int mt = 0; mt < 2; mt++) {
            int row = wm * 32 + mt * 16 + g;
            unsigned ah[4], al[4];
            ah[0] = AsH[cur][tig * PADW + row];
            ah[1] = AsH[cur][tig * PADW + row + 8];
            ah[2] = AsH[cur][(tig + 4) * PADW + row];
            ah[3] = AsH[cur][(tig + 4) * PADW + row + 8];
            al[0] = AsL[cur][tig * PADW + row];
            al[1] = AsL[cur][tig * PADW + row + 8];
            al[2] = AsL[cur][(tig + 4) * PADW + row];
            al[3] = AsL[cur][(tig + 4) * PADW + row + 8];
            #pragma unroll
            for (int nt = 0; nt < 8; nt++) {
                mma_bf16(acc[mt][nt], ah, bh[nt]);  // hi*hi
                mma_bf16(acc[mt][nt], al, bh[nt]);  // lo*hi
                mma_bf16(acc[mt][nt], ah, bl[nt]);  // hi*lo
            }
        }

        if (more) sts(cur ^ 1);
        __syncthreads();
        cur ^= 1;
    }

    // ---- epilogue ----
    #pragma unroll
    for (int mt = 0; mt < 2; mt++) {
        #pragma unroll
        for (int nt = 0; nt < 8; nt++) {
            int row0 = bm + wm * 32 + mt * 16 + g;
            int col0 = bn + wn * 64 + nt * 8 + tig * 2;
            #pragma unroll
            for (int h = 0; h < 2; h++) {
                int row = row0 + h * 8;
                if (row < M) {
                    #pragma unroll
                    for (int w = 0; w < 2; w++) {
                        int col = col0 + w;
                        if (col < N) {
                            float v = acc[mt][nt][h * 2 + w];
                            if (BIASF) v += bias[col];
                            if (SPLITK > 1) atomicAdd(&C[(size_t)row * N + col], v);
                            else            C[(size_t)row * N + col] = v;
                        }
                    }
                }
            }
        }
    }
}

// ---------------- LSTM gates (both directions in one launch) ----------------
__global__ void lstm_gates(const float* __restrict__ bih_f, const float* __restrict__ bhh_f,
                           const float* __restrict__ bih_b, const float* __restrict__ bhh_b,
                           int s)
{
    int i = blockIdx.x * blockDim.x + threadIdx.x;
    if (i >= 2 * BB * HH) return;
    int dir = i / (BB * HH);
    int rr  = i - dir * (BB * HH);
    int b   = rr / HH;
    int j   = rr - b * HH;
    int tt  = dir ? (TT - 1 - s) : s;

    const float* bi = dir ? bih_b : bih_f;
    const float* bh = dir ? bhh_b : bhh_f;

    size_t gb  = (size_t)dir * BB * G4 + (size_t)b * G4;
    size_t gib = (size_t)dir * BT * G4 + ((size_t)b * TT + tt) * G4;

    float xi = g_gg[gb +        j] + g_gi[gib +        j] + bi[j]          + bh[j];
    float xf = g_gg[gb +  HH  + j] + g_gi[gib +  HH  + j] + bi[HH + j]     + bh[HH + j];
    float xg = g_gg[gb + 2*HH + j] + g_gi[gib + 2*HH + j] + bi[2*HH + j]   + bh[2*HH + j];
    float xo = g_gg[gb + 3*HH + j] + g_gi[gib + 3*HH + j] + bi[3*HH + j]   + bh[3*HH + j];

    float ig = sigf(xi), fg = sigf(xf), cg = tanhfast(xg), og = sigf(xo);

    size_t hidx = (size_t)dir * BB * HH + rr;
    float cn = fg * g_cs[hidx] + ig * cg;
    float hn = og * tanhfast(cn);
    g_cs[hidx] = cn;
    g_h[hidx]  = hn;
    g_c[((size_t)b * TT + tt) * D2 + dir * HH + j] = hn;
}

// ---------------- row L2-normalize (warp per row) ----------------
__global__ void rownorm(const float* __restrict__ in, float* __restrict__ out, int R, int W) {
    int warp = threadIdx.x >> 5;
    int lane = threadIdx.x & 31;
    int row = blockIdx.x * 8 + warp;
    if (row >= R) return;
    const float* p = in + (size_t)row * W;
    float ss = 0.f;
    for (int cc = lane; cc < W; cc += 32) { float v = p[cc]; ss += v * v; }
    #pragma unroll
    for (int o = 16; o; o >>= 1) ss += __shfl_xor_sync(0xffffffffu, ss, o);
    float scale = 1.0f / fmaxf(sqrtf(ss), 1e-8f);
    float* q = out + (size_t)row * W;
    for (int cc = lane; cc < W; cc += 32) q[cc] = p[cc] * scale;
}

// ---------------- edge scatter-add: agg[dst] += m[src] ----------------
__global__ void scatter_add(const int* __restrict__ ei) {
    int i = blockIdx.x * blockDim.x + threadIdx.x;
    if (i >= NEDGE * (CC / 4)) return;
    int e  = i >> 8;
    int c4 = (i & 255) << 2;
    int src = ei[e];
    int dst = ei[NEDGE + e];
    float4 v = *(const float4*)&g_m[(size_t)src * CC + c4];
    float* a = &g_agg[(size_t)dst * CC + c4];
    atomicAdd(a + 0, v.x); atomicAdd(a + 1, v.y);
    atomicAdd(a + 2, v.z); atomicAdd(a + 3, v.w);
}

// ---------------- GRU cell update (in-place on g_hn) ----------------
__global__ void gru_gates(const float* __restrict__ bih, const float* __restrict__ bhh) {
    int i = blockIdx.x * blockDim.x + threadIdx.x;
    if (i >= BB * CC) return;
    int b = i >> 10;
    int j = i & 1023;
    size_t gb = (size_t)b * 3072;
    size_t gh = (size_t)BB * 3072 + gb;

    float ir  = g_gru[gb +        j] + bih[j];
    float iz  = g_gru[gb + 1024 + j] + bih[1024 + j];
    float in_ = g_gru[gb + 2048 + j] + bih[2048 + j];
    float hr  = g_gru[gh +        j] + bhh[j];
    float hz  = g_gru[gh + 1024 + j] + bhh[1024 + j];
    float hn  = g_gru[gh + 2048 + j] + bhh[2048 + j];

    float rg = sigf(ir + hr);
    float zg = sigf(iz + hz);
    float ng = tanhfast(in_ + rg * hn);
    float h = g_hn[i];
    g_hn[i] = (1.0f - zg) * ng + zg * h;
}

// ---------------- orchestration ----------------
extern "C" void kernel_launch(void* const* d_in, const int* in_sizes, int n_in,
                              void* d_out, int out_size)
{
    const int*   x        = (const int*)d_in[0];
    const int*   ei       = (const int*)d_in[1];
    const float* emb_tab  = (const float*)d_in[2];
    const float* Wih_f    = (const float*)d_in[3];
    const float* Whh_f    = (const float*)d_in[4];
    const float* bih_f    = (const float*)d_in[5];
    const float* bhh_f    = (const float*)d_in[6];
    const float* Wih_b    = (const float*)d_in[7];
    const float* Whh_b    = (const float*)d_in[8];
    const float* bih_b    = (const float*)d_in[9];
    const float* bhh_b    = (const float*)d_in[10];
    const float* label    = (const float*)d_in[11];
    const float* ggc_w    = (const float*)d_in[12];
    const float* gru_Wih  = (const float*)d_in[13];
    const float* gru_Whh  = (const float*)d_in[14];
    const float* gru_bih  = (const float*)d_in[15];
    const float* gru_bhh  = (const float*)d_in[16];
    const float* proj_W   = (const float*)d_in[17];
    const float* proj_b   = (const float*)d_in[18];
    float* out = (float*)d_out;

    float *p_gi, *p_c, *p_h, *p_cs, *p_gg, *p_lnn, *p_hn, *p_m, *p_agg, *p_gru;
    cudaGetSymbolAddress((void**)&p_gi,  g_gi);
    cudaGetSymbolAddress((void**)&p_c,   g_c);
    cudaGetSymbolAddress((void**)&p_h,   g_h);
    cudaGetSymbolAddress((void**)&p_cs,  g_cs);
    cudaGetSymbolAddress((void**)&p_gg,  g_gg);
    cudaGetSymbolAddress((void**)&p_lnn, g_lnn);
    cudaGetSymbolAddress((void**)&p_hn,  g_hn);
    cudaGetSymbolAddress((void**)&p_m,   g_m);
    cudaGetSymbolAddress((void**)&p_agg, g_agg);
    cudaGetSymbolAddress((void**)&p_gru, g_gru);

    const int TPB = 256;

    // 0) zero LSTM states
    zerok<<<(2 * BB * HH + TPB - 1) / TPB, TPB>>>(p_h, 2 * BB * HH);
    zerok<<<(2 * BB * HH + TPB - 1) / TPB, TPB>>>(p_cs, 2 * BB * HH);

    // 1) input-to-hidden GEMMs with fused embedding gather (NT, GIDX)
    {
        dim3 grid((G4 + 127) / 128, (BT + 127) / 128, 2);
        gemm_bf<0, 0, 0, 1, 1><<<grid, 256>>>(emb_tab, Wih_f, p_gi,
                                              emb_tab, Wih_b, p_gi + (size_t)BT * G4,
                                              nullptr, x, BT, G4, EE);
    }

    // 2) recurrence: 64 steps, both directions batched (z=2)
    for (int s = 0; s < TT; s++) {
        dim3 grid((G4 + 127) / 128, (BB + 127) / 128, 2);
        gemm_bf<0, 0, 0, 1, 0><<<grid, 256>>>(p_h,                   Whh_f, p_gg,
                                              p_h + (size_t)BB * HH, Whh_b, p_gg + (size_t)BB * G4,
                                              nullptr, nullptr, BB, G4, HH);
        lstm_gates<<<(2 * BB * HH + TPB - 1) / TPB, TPB>>>(bih_f, bhh_f, bih_b, bhh_b, s);
    }

    // 3) normalize c rows (in place) and label rows
    rownorm<<<(BT + 7) / 8, 256>>>(p_c, p_c, BT, D2);
    rownorm<<<(CC + 7) / 8, 256>>>(label, p_lnn, CC, D2);

    // 4) cosine similarity folded GEMM: [B, 38400] x periodic [1024, 600], split-K x4
    zerok<<<(BB * CC + TPB - 1) / TPB, TPB>>>(p_hn, BB * CC);
    {
        dim3 grid((CC + 127) / 128, (BB + 127) / 128, 4);
        gemm_bf<0, D2, 0, 4, 0><<<grid, 256>>>(p_c, p_lnn, p_hn,
                                               p_c, p_lnn, p_hn,
                                               nullptr, nullptr, BB, CC, KCOS);
    }

    // 5) GatedGraphConv, 2 layers
    for (int layer = 0; layer < 2; layer++) {
        // m = h @ W[layer]   (NN)
        {
            dim3 grid((CC + 127) / 128, (BB + 127) / 128, 1);
            gemm_bf<1, 0, 0, 1, 0><<<grid, 256>>>(p_hn, ggc_w + (size_t)layer * CC * CC, p_m,
                                                  p_hn, ggc_w + (size_t)layer * CC * CC, p_m,
                                                  nullptr, nullptr, BB, CC, CC);
        }
        // scatter-add
        zerok<<<(BB * CC + TPB - 1) / TPB, TPB>>>(p_agg, BB * CC);
        scatter_add<<<(NEDGE * (CC / 4) + TPB - 1) / TPB, TPB>>>(ei);
        // GRU gate GEMMs (z=0: agg@Wih^T, z=1: h@Whh^T)
        {
            dim3 grid((3072 + 127) / 128, (BB + 127) / 128, 2);
            gemm_bf<0, 0, 0, 1, 0><<<grid, 256>>>(p_agg, gru_Wih, p_gru,
                                                  p_hn,  gru_Whh, p_gru + (size_t)BB * 3072,
                                                  nullptr, nullptr, BB, 3072, CC);
        }
        gru_gates<<<(BB * CC + TPB - 1) / TPB, TPB>>>(gru_bih, gru_bhh);
    }

    // 6) projection with bias -> d_out
    {
        dim3 grid((CC + 127) / 128, (BB + 127) / 128, 1);
        gemm_bf<0, 0, 1, 1, 0><<<grid, 256>>>(p_hn, proj_W, out,
                                              p_hn, proj_W, out,
                                              proj_b, nullptr, BB, CC, CC);
    }
}